// round 1
// baseline (speedup 1.0000x reference)
#include <cuda_runtime.h>

#define D      128
#define NN     20000
#define NE     600000
#define ESZ    20

// ---------------- scratch (device globals; no allocations allowed) ----------
__device__ float g_h1[NN * D];        // silu(s@Wm1+bm1)
__device__ float g_so[NN * 3 * D];    // scalar_output
__device__ float g_uv[NN * 3 * D];    // Uv
__device__ float g_vvsq[NN * D];      // sum_axis Vv^2
__device__ float g_ip[NN * D];        // sum_axis Uv*Vv
__device__ float g_h2[NN * D];        // silu([s,Vvsq]@Wa1+ba1)

__device__ __forceinline__ float silu_f(float x) {
    return x / (1.0f + __expf(-x));
}

// ---------------- kernel 1: init output with residuals -----------------------
__global__ void k_init(const float* __restrict__ ns, const float* __restrict__ nv,
                       float* __restrict__ out) {
    const float4* a = (const float4*)ns;
    const float4* b = (const float4*)nv;
    float4* os = (float4*)out;
    float4* ov = os + (NN * D) / 4;
    const int ts = NN * D / 4;
    const int tv = NN * 3 * D / 4;
    for (int i = blockIdx.x * blockDim.x + threadIdx.x; i < ts; i += gridDim.x * blockDim.x)
        os[i] = a[i];
    for (int i = blockIdx.x * blockDim.x + threadIdx.x; i < tv; i += gridDim.x * blockDim.x)
        ov[i] = b[i];
}

// ---------------- kernel 2: h1 = silu(ns @ Wm1 + bm1) ------------------------
// smem: W[128*128] | b[128] | x[2*128]
__global__ void k_mlp1(const float* __restrict__ x, const float* __restrict__ W,
                       const float* __restrict__ b) {
    extern __shared__ float sm[];
    float* Ws = sm;                 // 16384
    float* bs = sm + 16384;         // 128
    float* xs = sm + 16512;         // 256
    int tid = threadIdx.x, g = tid >> 7, c = tid & 127;
    for (int i = tid; i < D * D; i += 256) Ws[i] = W[i];
    if (tid < D) bs[tid] = b[tid];
    __syncthreads();
    int stride = gridDim.x * 2;
    int iters = (NN + stride - 1) / stride;
    for (int it = 0; it < iters; ++it) {
        int n = it * stride + blockIdx.x * 2 + g;
        bool act = n < NN;
        if (act) xs[g * D + c] = x[(long)n * D + c];
        __syncthreads();
        if (act) {
            float acc = bs[c];
#pragma unroll 8
            for (int k = 0; k < D; k++) acc += xs[g * D + k] * Ws[k * D + c];
            g_h1[(long)n * D + c] = silu_f(acc);
        }
        __syncthreads();
    }
}

// ---------------- kernel 3: scalar_output = h1 @ Wm2 + bm2 -------------------
// smem: W[128*384] | b[384] | x[2*128]
__global__ void k_mlp2(const float* __restrict__ W, const float* __restrict__ b) {
    extern __shared__ float sm[];
    float* Ws = sm;                 // 49152
    float* bs = sm + 49152;         // 384
    float* xs = sm + 49536;         // 256
    int tid = threadIdx.x, g = tid >> 7, c = tid & 127;
    for (int i = tid; i < D * 3 * D; i += 256) Ws[i] = W[i];
    for (int i = tid; i < 3 * D; i += 256) bs[i] = b[i];
    __syncthreads();
    int stride = gridDim.x * 2;
    int iters = (NN + stride - 1) / stride;
    for (int it = 0; it < iters; ++it) {
        int n = it * stride + blockIdx.x * 2 + g;
        bool act = n < NN;
        if (act) xs[g * D + c] = g_h1[(long)n * D + c];
        __syncthreads();
        if (act) {
            float a0 = bs[c], a1 = bs[c + 128], a2 = bs[c + 256];
#pragma unroll 8
            for (int k = 0; k < D; k++) {
                float h = xs[g * D + k];
                const float* w = &Ws[k * 384];
                a0 += h * w[c];
                a1 += h * w[c + 128];
                a2 += h * w[c + 256];
            }
            long nb = (long)n * 384;
            g_so[nb + c] = a0;
            g_so[nb + c + 128] = a1;
            g_so[nb + c + 256] = a2;
        }
        __syncthreads();
    }
}

// ---------------- kernel 4: fused edge filter + gather + scatter -------------
// 2 edges per 256-thread block iteration; Wf staged in static smem.
__global__ void k_edge(const float* __restrict__ es, const float* __restrict__ ev,
                       const float* __restrict__ en, const int* __restrict__ ei,
                       const float* __restrict__ Wf, const float* __restrict__ bf,
                       const float* __restrict__ nv, float* __restrict__ out) {
    __shared__ float Ws[ESZ * 384];
    __shared__ float bs[384];
    __shared__ float ess[2][ESZ];
    __shared__ float evs[2][4];
    __shared__ float fcs[2];
    __shared__ int sds[2][2];
    float* out_s = out;
    float* out_v = out + (long)NN * D;
    int tid = threadIdx.x, g = tid >> 7, c = tid & 127;
    for (int i = tid; i < ESZ * 384; i += 256) Ws[i] = Wf[i];
    for (int i = tid; i < 384; i += 256) bs[i] = bf[i];
    __syncthreads();
    int stride = gridDim.x * 2;
    int iters = (NE + stride - 1) / stride;
    for (int it = 0; it < iters; ++it) {
        int e = it * stride + blockIdx.x * 2 + g;
        bool act = e < NE;
        if (act) {
            if (c < ESZ) {
                ess[g][c] = es[(long)e * ESZ + c];
            } else if (c < 23) {
                evs[g][c - 20] = ev[(long)e * 3 + (c - 20)];
            } else if (c == 23) {
                float r = en[e];
                fcs[g] = (r < 5.0f) ? 0.5f * (cospif(r * 0.2f) + 1.0f) : 0.0f;
            } else if (c == 24) {
                sds[g][0] = ei[(long)e * 2];
            } else if (c == 25) {
                sds[g][1] = ei[(long)e * 2 + 1];
            }
        }
        __syncthreads();
        if (act) {
            int src = sds[g][0], dst = sds[g][1];
            float fc = fcs[g];
            float f0 = bs[c], f1 = bs[c + 128], f2 = bs[c + 256];
#pragma unroll
            for (int k = 0; k < ESZ; k++) {
                float ek = ess[g][k];
                const float* w = &Ws[k * 384];
                f0 += ek * w[c];
                f1 += ek * w[c + 128];
                f2 += ek * w[c + 256];
            }
            long sb = (long)src * 384;
            float gate_n = f0 * fc * __ldg(&g_so[sb + c]);
            float gate_e = f1 * fc * __ldg(&g_so[sb + c + 128]);
            float msca   = f2 * fc * __ldg(&g_so[sb + c + 256]);
            atomicAdd(&out_s[(long)dst * D + c], msca);
            long ob = (long)dst * 384;
#pragma unroll
            for (int ax = 0; ax < 3; ++ax) {
                float nvv = __ldg(&nv[sb + ax * D + c]);
                float mv = nvv * gate_n + gate_e * evs[g][ax];
                atomicAdd(&out_v[ob + ax * D + c], mv);
            }
        }
        __syncthreads();
    }
}

// ---------------- kernel 5: Uv, |Vv|^2, <Uv,Vv> ------------------------------
// smem: WU[16384] | WV[16384] | v[2*384]
__global__ void k_uv(const float* __restrict__ WU, const float* __restrict__ WV,
                     const float* __restrict__ out) {
    extern __shared__ float sm[];
    float* WUs = sm;
    float* WVs = sm + 16384;
    float* vs = sm + 32768;
    const float* v_in = out + (long)NN * D;
    int tid = threadIdx.x, g = tid >> 7, c = tid & 127;
    for (int i = tid; i < 16384; i += 256) {
        WUs[i] = WU[i];
        WVs[i] = WV[i];
    }
    __syncthreads();
    int stride = gridDim.x * 2;
    int iters = (NN + stride - 1) / stride;
    for (int it = 0; it < iters; ++it) {
        int n = it * stride + blockIdx.x * 2 + g;
        bool act = n < NN;
        if (act) {
            long b = (long)n * 384;
            vs[g * 384 + c]       = v_in[b + c];
            vs[g * 384 + c + 128] = v_in[b + c + 128];
            vs[g * 384 + c + 256] = v_in[b + c + 256];
        }
        __syncthreads();
        if (act) {
            float u0 = 0, u1 = 0, u2 = 0, w0 = 0, w1 = 0, w2 = 0;
#pragma unroll 4
            for (int k = 0; k < D; k++) {
                float wu = WUs[k * D + c], wv = WVs[k * D + c];
                float v0 = vs[g * 384 + k];
                float v1 = vs[g * 384 + 128 + k];
                float v2 = vs[g * 384 + 256 + k];
                u0 += v0 * wu; u1 += v1 * wu; u2 += v2 * wu;
                w0 += v0 * wv; w1 += v1 * wv; w2 += v2 * wv;
            }
            long b = (long)n * 384;
            g_uv[b + c] = u0;
            g_uv[b + c + 128] = u1;
            g_uv[b + c + 256] = u2;
            g_vvsq[(long)n * D + c] = w0 * w0 + w1 * w1 + w2 * w2;
            g_ip[(long)n * D + c]   = u0 * w0 + u1 * w1 + u2 * w2;
        }
        __syncthreads();
    }
}

// ---------------- kernel 6: h2 = silu([s, Vvsq] @ Wa1 + ba1) -----------------
// smem: W[256*128] | b[128] | x[2*256]
__global__ void k_a1(const float* __restrict__ W, const float* __restrict__ b,
                     const float* __restrict__ out) {
    extern __shared__ float sm[];
    float* Ws = sm;                 // 32768
    float* bs = sm + 32768;         // 128
    float* xs = sm + 32896;         // 512
    int tid = threadIdx.x, g = tid >> 7, c = tid & 127;
    for (int i = tid; i < 256 * D; i += 256) Ws[i] = W[i];
    if (tid < D) bs[tid] = b[tid];
    __syncthreads();
    int stride = gridDim.x * 2;
    int iters = (NN + stride - 1) / stride;
    for (int it = 0; it < iters; ++it) {
        int n = it * stride + blockIdx.x * 2 + g;
        bool act = n < NN;
        if (act) {
            xs[g * 256 + c]       = out[(long)n * D + c];
            xs[g * 256 + 128 + c] = g_vvsq[(long)n * D + c];
        }
        __syncthreads();
        if (act) {
            float a = bs[c];
#pragma unroll 8
            for (int k = 0; k < 256; k++) a += xs[g * 256 + k] * Ws[k * D + c];
            g_h2[(long)n * D + c] = silu_f(a);
        }
        __syncthreads();
    }
}

// ---------------- kernel 7: a = h2 @ Wa2 + ba2, final in-place update --------
// smem: W[128*384] | b[384] | h[2*128]
__global__ void k_a2(const float* __restrict__ W, const float* __restrict__ b,
                     float* __restrict__ out) {
    extern __shared__ float sm[];
    float* Ws = sm;
    float* bs = sm + 49152;
    float* hs = sm + 49536;
    float* out_s = out;
    float* out_v = out + (long)NN * D;
    int tid = threadIdx.x, g = tid >> 7, c = tid & 127;
    for (int i = tid; i < D * 384; i += 256) Ws[i] = W[i];
    for (int i = tid; i < 384; i += 256) bs[i] = b[i];
    __syncthreads();
    int stride = gridDim.x * 2;
    int iters = (NN + stride - 1) / stride;
    for (int it = 0; it < iters; ++it) {
        int n = it * stride + blockIdx.x * 2 + g;
        bool act = n < NN;
        if (act) hs[g * D + c] = g_h2[(long)n * D + c];
        __syncthreads();
        if (act) {
            float a0 = bs[c], a1 = bs[c + 128], a2 = bs[c + 256];
#pragma unroll 8
            for (int k = 0; k < D; k++) {
                float h = hs[g * D + k];
                const float* w = &Ws[k * 384];
                a0 += h * w[c];
                a1 += h * w[c + 128];
                a2 += h * w[c + 256];
            }
            long sb = (long)n * D;
            float ip = g_ip[sb + c];
            out_s[sb + c] = out_s[sb + c] + a0 + a1 * ip;
            long vb = (long)n * 384;
#pragma unroll
            for (int ax = 0; ax < 3; ax++) {
                float uv = g_uv[vb + ax * D + c];
                out_v[vb + ax * D + c] += a2 * uv;
            }
        }
        __syncthreads();
    }
}

// ---------------- launch ------------------------------------------------------
extern "C" void kernel_launch(void* const* d_in, const int* in_sizes, int n_in,
                              void* d_out, int out_size) {
    const float* ns  = (const float*)d_in[0];
    const float* nv  = (const float*)d_in[1];
    const float* es  = (const float*)d_in[2];
    const float* ev  = (const float*)d_in[3];
    const float* en  = (const float*)d_in[4];
    const int*   ei  = (const int*)d_in[5];
    const float* Wf  = (const float*)d_in[6];
    const float* bf  = (const float*)d_in[7];
    const float* Wm1 = (const float*)d_in[8];
    const float* bm1 = (const float*)d_in[9];
    const float* Wm2 = (const float*)d_in[10];
    const float* bm2 = (const float*)d_in[11];
    const float* WU  = (const float*)d_in[12];
    const float* WV  = (const float*)d_in[13];
    const float* Wa1 = (const float*)d_in[14];
    const float* ba1 = (const float*)d_in[15];
    const float* Wa2 = (const float*)d_in[16];
    const float* ba2 = (const float*)d_in[17];
    float* out = (float*)d_out;

    const int SM_MLP1 = (16384 + 128 + 256) * 4;          // 67072
    const int SM_MLP2 = (49152 + 384 + 256) * 4;          // 199168
    const int SM_UV   = (32768 + 768) * 4;                // 134144
    const int SM_A1   = (32768 + 128 + 512) * 4;          // 133632
    const int SM_A2   = (49152 + 384 + 256) * 4;          // 199168

    cudaFuncSetAttribute(k_mlp1, cudaFuncAttributeMaxDynamicSharedMemorySize, SM_MLP1);
    cudaFuncSetAttribute(k_mlp2, cudaFuncAttributeMaxDynamicSharedMemorySize, SM_MLP2);
    cudaFuncSetAttribute(k_uv,   cudaFuncAttributeMaxDynamicSharedMemorySize, SM_UV);
    cudaFuncSetAttribute(k_a1,   cudaFuncAttributeMaxDynamicSharedMemorySize, SM_A1);
    cudaFuncSetAttribute(k_a2,   cudaFuncAttributeMaxDynamicSharedMemorySize, SM_A2);

    k_init<<<2048, 256>>>(ns, nv, out);
    k_mlp1<<<296, 256, SM_MLP1>>>(ns, Wm1, bm1);
    k_mlp2<<<296, 256, SM_MLP2>>>(Wm2, bm2);
    k_edge<<<1184, 256>>>(es, ev, en, ei, Wf, bf, nv, out);
    k_uv<<<296, 256, SM_UV>>>(WU, WV, out);
    k_a1<<<296, 256, SM_A1>>>(Wa1, ba1, out);
    k_a2<<<296, 256, SM_A2>>>(Wa2, ba2, out);
}

// round 2
// speedup vs baseline: 1.2177x; 1.2177x over previous
#include <cuda_runtime.h>

#define D      128
#define NN     20000
#define NE     600000
#define ESZ    20
#define SUBS   5                 // edges per block-iteration in k_edge
#define EB     (SUBS * 96)       // 480 threads: 15 warps = 5 edges x 3 role-warps

// ---------------- scratch (device globals; no allocations allowed) ----------
__device__ float g_h1[NN * D];        // silu(s@Wm1+bm1)
__device__ float g_so[NN * 3 * D];    // scalar_output
__device__ float g_uv[NN * 3 * D];    // Uv
__device__ float g_vvsq[NN * D];      // sum_axis Vv^2
__device__ float g_ip[NN * D];        // sum_axis Uv*Vv
__device__ float g_h2[NN * D];        // silu([s,Vvsq]@Wa1+ba1)

__device__ __forceinline__ float silu_f(float x) {
    return x / (1.0f + __expf(-x));
}

__device__ __forceinline__ void red4(float* p, float a, float b, float c, float d) {
    asm volatile("red.global.add.v4.f32 [%0], {%1,%2,%3,%4};"
                 :: "l"(p), "f"(a), "f"(b), "f"(c), "f"(d) : "memory");
}

// ---------------- kernel 1: init output with residuals -----------------------
__global__ void k_init(const float* __restrict__ ns, const float* __restrict__ nv,
                       float* __restrict__ out) {
    const float4* a = (const float4*)ns;
    const float4* b = (const float4*)nv;
    float4* os = (float4*)out;
    float4* ov = os + (NN * D) / 4;
    const int ts = NN * D / 4;
    const int tv = NN * 3 * D / 4;
    for (int i = blockIdx.x * blockDim.x + threadIdx.x; i < ts; i += gridDim.x * blockDim.x)
        os[i] = a[i];
    for (int i = blockIdx.x * blockDim.x + threadIdx.x; i < tv; i += gridDim.x * blockDim.x)
        ov[i] = b[i];
}

// ---------------- kernel 2: h1 = silu(ns @ Wm1 + bm1) ------------------------
// 512 threads, 4 nodes / iter.  smem: W[128*128] | b[128] | x[4*128]
__global__ void k_mlp1(const float* __restrict__ x, const float* __restrict__ W,
                       const float* __restrict__ b) {
    extern __shared__ float sm[];
    float* Ws = sm;                 // 16384
    float* bs = sm + 16384;         // 128
    float* xs = sm + 16512;         // 512
    int tid = threadIdx.x, g = tid >> 7, c = tid & 127;
    for (int i = tid; i < D * D; i += 512) Ws[i] = W[i];
    if (tid < D) bs[tid] = b[tid];
    __syncthreads();
    int stride = gridDim.x * 4;
    int iters = (NN + stride - 1) / stride;
    for (int it = 0; it < iters; ++it) {
        int n = it * stride + blockIdx.x * 4 + g;
        bool act = n < NN;
        if (act) xs[g * D + c] = x[(long)n * D + c];
        __syncthreads();
        if (act) {
            float acc = bs[c];
#pragma unroll 8
            for (int k = 0; k < D; k++) acc += xs[g * D + k] * Ws[k * D + c];
            g_h1[(long)n * D + c] = silu_f(acc);
        }
        __syncthreads();
    }
}

// ---------------- kernel 3: scalar_output = h1 @ Wm2 + bm2 -------------------
// smem: W[128*384] | b[384] | x[4*128]
__global__ void k_mlp2(const float* __restrict__ W, const float* __restrict__ b) {
    extern __shared__ float sm[];
    float* Ws = sm;                 // 49152
    float* bs = sm + 49152;         // 384
    float* xs = sm + 49536;         // 512
    int tid = threadIdx.x, g = tid >> 7, c = tid & 127;
    for (int i = tid; i < D * 3 * D; i += 512) Ws[i] = W[i];
    for (int i = tid; i < 3 * D; i += 512) bs[i] = b[i];
    __syncthreads();
    int stride = gridDim.x * 4;
    int iters = (NN + stride - 1) / stride;
    for (int it = 0; it < iters; ++it) {
        int n = it * stride + blockIdx.x * 4 + g;
        bool act = n < NN;
        if (act) xs[g * D + c] = g_h1[(long)n * D + c];
        __syncthreads();
        if (act) {
            float a0 = bs[c], a1 = bs[c + 128], a2 = bs[c + 256];
#pragma unroll 8
            for (int k = 0; k < D; k++) {
                float h = xs[g * D + k];
                const float* w = &Ws[k * 384];
                a0 += h * w[c];
                a1 += h * w[c + 128];
                a2 += h * w[c + 256];
            }
            long nb = (long)n * 384;
            g_so[nb + c] = a0;
            g_so[nb + c + 128] = a1;
            g_so[nb + c + 256] = a2;
        }
        __syncthreads();
    }
}

// ---------------- kernel 4: fused edge filter + gather + scatter -------------
// 15 warps/block = 5 edges x 3 role-warps.  role b owns Wf columns [b*128, b*128+128).
// Each lane owns 4 consecutive channels; Wf slice lives in 20 float4 registers.
__global__ void __launch_bounds__(EB, 1)
k_edge(const float* __restrict__ es, const float* __restrict__ ev,
       const float* __restrict__ en, const int* __restrict__ ei,
       const float* __restrict__ Wf, const float* __restrict__ bf,
       const float* __restrict__ nv, float* __restrict__ out) {
    __shared__ float4 geb[2][SUBS][32];   // gate_edges hand-off, double-buffered
    int tid  = threadIdx.x;
    int warp = tid >> 5, lane = tid & 31;
    int sub  = warp / 3, role = warp % 3;

    // per-lane weight slice: Wf[k][role*128 + lane*4 .. +3]
    float4 Wreg[ESZ];
    const float* wb = Wf + role * 128 + lane * 4;
#pragma unroll
    for (int k = 0; k < ESZ; k++) Wreg[k] = *(const float4*)(wb + k * 384);
    float4 bfr = *(const float4*)(bf + role * 128 + lane * 4);

    float* out_s = out;
    float* out_v = out + (size_t)NN * D;

    int estride = gridDim.x * SUBS;
    int p = 0;
    for (int base = blockIdx.x * SUBS; base < NE; base += estride) {
        int e = base + sub;
        bool act = e < NE;
        float4 m = {0.f, 0.f, 0.f, 0.f};
        int src = 0, dst = 0;
        if (act) {
            float esv = (lane < ESZ) ? __ldg(es + (size_t)e * ESZ + lane) : 0.f;
            src = __ldg(ei + 2 * (size_t)e);
            dst = __ldg(ei + 2 * (size_t)e + 1);
            float r = __ldg(en + e);
            float fc = (r < 5.0f) ? 0.5f * (cospif(r * 0.2f) + 1.0f) : 0.0f;
            float4 f = bfr;
#pragma unroll
            for (int k = 0; k < ESZ; k++) {
                float ek = __shfl_sync(0xffffffffu, esv, k);
                f.x += ek * Wreg[k].x;
                f.y += ek * Wreg[k].y;
                f.z += ek * Wreg[k].z;
                f.w += ek * Wreg[k].w;
            }
            float4 so4 = __ldg((const float4*)(g_so + (size_t)src * 384 + role * 128) + lane);
            m.x = f.x * fc * so4.x;
            m.y = f.y * fc * so4.y;
            m.z = f.z * fc * so4.z;
            m.w = f.w * fc * so4.w;
            if (role == 2) {
                red4(out_s + (size_t)dst * D + lane * 4, m.x, m.y, m.z, m.w);
            } else if (role == 1) {
                geb[p][sub][lane] = m;   // gate_edges
            }
        }
        __syncthreads();
        if (act && role == 0) {
            float4 ge = geb[p][sub][lane];
            float ev0 = __ldg(ev + 3 * (size_t)e);
            float ev1 = __ldg(ev + 3 * (size_t)e + 1);
            float ev2 = __ldg(ev + 3 * (size_t)e + 2);
            const float4* nvp = (const float4*)(nv + (size_t)src * 384) + lane;
            float4 n0 = __ldg(nvp);
            float4 n1 = __ldg(nvp + 32);
            float4 n2 = __ldg(nvp + 64);
            float* ovb = out_v + (size_t)dst * 384 + lane * 4;
            red4(ovb,       m.x * n0.x + ge.x * ev0, m.y * n0.y + ge.y * ev0,
                            m.z * n0.z + ge.z * ev0, m.w * n0.w + ge.w * ev0);
            red4(ovb + 128, m.x * n1.x + ge.x * ev1, m.y * n1.y + ge.y * ev1,
                            m.z * n1.z + ge.z * ev1, m.w * n1.w + ge.w * ev1);
            red4(ovb + 256, m.x * n2.x + ge.x * ev2, m.y * n2.y + ge.y * ev2,
                            m.z * n2.z + ge.z * ev2, m.w * n2.w + ge.w * ev2);
        }
        p ^= 1;
    }
}

// ---------------- kernel 5: Uv, |Vv|^2, <Uv,Vv> ------------------------------
// smem: WU[16384] | WV[16384] | v[4*384]
__global__ void k_uv(const float* __restrict__ WU, const float* __restrict__ WV,
                     const float* __restrict__ out) {
    extern __shared__ float sm[];
    float* WUs = sm;
    float* WVs = sm + 16384;
    float* vs = sm + 32768;
    const float* v_in = out + (long)NN * D;
    int tid = threadIdx.x, g = tid >> 7, c = tid & 127;
    for (int i = tid; i < 16384; i += 512) {
        WUs[i] = WU[i];
        WVs[i] = WV[i];
    }
    __syncthreads();
    int stride = gridDim.x * 4;
    int iters = (NN + stride - 1) / stride;
    for (int it = 0; it < iters; ++it) {
        int n = it * stride + blockIdx.x * 4 + g;
        bool act = n < NN;
        if (act) {
            long b = (long)n * 384;
            vs[g * 384 + c]       = v_in[b + c];
            vs[g * 384 + c + 128] = v_in[b + c + 128];
            vs[g * 384 + c + 256] = v_in[b + c + 256];
        }
        __syncthreads();
        if (act) {
            float u0 = 0, u1 = 0, u2 = 0, w0 = 0, w1 = 0, w2 = 0;
#pragma unroll 4
            for (int k = 0; k < D; k++) {
                float wu = WUs[k * D + c], wv = WVs[k * D + c];
                float v0 = vs[g * 384 + k];
                float v1 = vs[g * 384 + 128 + k];
                float v2 = vs[g * 384 + 256 + k];
                u0 += v0 * wu; u1 += v1 * wu; u2 += v2 * wu;
                w0 += v0 * wv; w1 += v1 * wv; w2 += v2 * wv;
            }
            long b = (long)n * 384;
            g_uv[b + c] = u0;
            g_uv[b + c + 128] = u1;
            g_uv[b + c + 256] = u2;
            g_vvsq[(long)n * D + c] = w0 * w0 + w1 * w1 + w2 * w2;
            g_ip[(long)n * D + c]   = u0 * w0 + u1 * w1 + u2 * w2;
        }
        __syncthreads();
    }
}

// ---------------- kernel 6: h2 = silu([s, Vvsq] @ Wa1 + ba1) -----------------
// smem: W[256*128] | b[128] | x[4*256]
__global__ void k_a1(const float* __restrict__ W, const float* __restrict__ b,
                     const float* __restrict__ out) {
    extern __shared__ float sm[];
    float* Ws = sm;                 // 32768
    float* bs = sm + 32768;         // 128
    float* xs = sm + 32896;         // 1024
    int tid = threadIdx.x, g = tid >> 7, c = tid & 127;
    for (int i = tid; i < 256 * D; i += 512) Ws[i] = W[i];
    if (tid < D) bs[tid] = b[tid];
    __syncthreads();
    int stride = gridDim.x * 4;
    int iters = (NN + stride - 1) / stride;
    for (int it = 0; it < iters; ++it) {
        int n = it * stride + blockIdx.x * 4 + g;
        bool act = n < NN;
        if (act) {
            xs[g * 256 + c]       = out[(long)n * D + c];
            xs[g * 256 + 128 + c] = g_vvsq[(long)n * D + c];
        }
        __syncthreads();
        if (act) {
            float a = bs[c];
#pragma unroll 8
            for (int k = 0; k < 256; k++) a += xs[g * 256 + k] * Ws[k * D + c];
            g_h2[(long)n * D + c] = silu_f(a);
        }
        __syncthreads();
    }
}

// ---------------- kernel 7: a = h2 @ Wa2 + ba2, final in-place update --------
// smem: W[128*384] | b[384] | h[4*128]
__global__ void k_a2(const float* __restrict__ W, const float* __restrict__ b,
                     float* __restrict__ out) {
    extern __shared__ float sm[];
    float* Ws = sm;
    float* bs = sm + 49152;
    float* hs = sm + 49536;
    float* out_s = out;
    float* out_v = out + (long)NN * D;
    int tid = threadIdx.x, g = tid >> 7, c = tid & 127;
    for (int i = tid; i < D * 384; i += 512) Ws[i] = W[i];
    for (int i = tid; i < 384; i += 512) bs[i] = b[i];
    __syncthreads();
    int stride = gridDim.x * 4;
    int iters = (NN + stride - 1) / stride;
    for (int it = 0; it < iters; ++it) {
        int n = it * stride + blockIdx.x * 4 + g;
        bool act = n < NN;
        if (act) hs[g * D + c] = g_h2[(long)n * D + c];
        __syncthreads();
        if (act) {
            float a0 = bs[c], a1 = bs[c + 128], a2 = bs[c + 256];
#pragma unroll 8
            for (int k = 0; k < D; k++) {
                float h = hs[g * D + k];
                const float* w = &Ws[k * 384];
                a0 += h * w[c];
                a1 += h * w[c + 128];
                a2 += h * w[c + 256];
            }
            long sb = (long)n * D;
            float ip = g_ip[sb + c];
            out_s[sb + c] = out_s[sb + c] + a0 + a1 * ip;
            long vb = (long)n * 384;
#pragma unroll
            for (int ax = 0; ax < 3; ax++) {
                float uv = g_uv[vb + ax * D + c];
                out_v[vb + ax * D + c] += a2 * uv;
            }
        }
        __syncthreads();
    }
}

// ---------------- launch ------------------------------------------------------
extern "C" void kernel_launch(void* const* d_in, const int* in_sizes, int n_in,
                              void* d_out, int out_size) {
    const float* ns  = (const float*)d_in[0];
    const float* nv  = (const float*)d_in[1];
    const float* es  = (const float*)d_in[2];
    const float* ev  = (const float*)d_in[3];
    const float* en  = (const float*)d_in[4];
    const int*   ei  = (const int*)d_in[5];
    const float* Wf  = (const float*)d_in[6];
    const float* bf  = (const float*)d_in[7];
    const float* Wm1 = (const float*)d_in[8];
    const float* bm1 = (const float*)d_in[9];
    const float* Wm2 = (const float*)d_in[10];
    const float* bm2 = (const float*)d_in[11];
    const float* WU  = (const float*)d_in[12];
    const float* WV  = (const float*)d_in[13];
    const float* Wa1 = (const float*)d_in[14];
    const float* ba1 = (const float*)d_in[15];
    const float* Wa2 = (const float*)d_in[16];
    const float* ba2 = (const float*)d_in[17];
    float* out = (float*)d_out;

    const int SM_MLP1 = (16384 + 128 + 512) * 4;
    const int SM_MLP2 = (49152 + 384 + 512) * 4;
    const int SM_UV   = (32768 + 4 * 384) * 4;
    const int SM_A1   = (32768 + 128 + 1024) * 4;
    const int SM_A2   = (49152 + 384 + 512) * 4;

    cudaFuncSetAttribute(k_mlp1, cudaFuncAttributeMaxDynamicSharedMemorySize, SM_MLP1);
    cudaFuncSetAttribute(k_mlp2, cudaFuncAttributeMaxDynamicSharedMemorySize, SM_MLP2);
    cudaFuncSetAttribute(k_uv,   cudaFuncAttributeMaxDynamicSharedMemorySize, SM_UV);
    cudaFuncSetAttribute(k_a1,   cudaFuncAttributeMaxDynamicSharedMemorySize, SM_A1);
    cudaFuncSetAttribute(k_a2,   cudaFuncAttributeMaxDynamicSharedMemorySize, SM_A2);

    k_init<<<2048, 256>>>(ns, nv, out);
    k_mlp1<<<148, 512, SM_MLP1>>>(ns, Wm1, bm1);
    k_mlp2<<<148, 512, SM_MLP2>>>(Wm2, bm2);
    k_edge<<<148, EB>>>(es, ev, en, ei, Wf, bf, nv, out);
    k_uv<<<148, 512, SM_UV>>>(WU, WV, out);
    k_a1<<<148, 512, SM_A1>>>(Wa1, ba1, out);
    k_a2<<<148, 512, SM_A2>>>(Wa2, ba2, out);
}

// round 3
// speedup vs baseline: 1.9127x; 1.5708x over previous
#include <cuda_runtime.h>

#define D      128
#define NN     20000
#define NE     600000
#define ESZ    20

// ---------------- scratch (device globals; no allocations allowed) ----------
__device__ float g_h1[NN * D];        // silu(s@Wm1+bm1)
__device__ float g_so[NN * 3 * D];    // scalar_output
__device__ float g_uv[NN * 3 * D];    // Uv
__device__ float g_vvsq[NN * D];      // sum_axis Vv^2
__device__ float g_ip[NN * D];        // sum_axis Uv*Vv
__device__ float g_h2[NN * D];        // silu([s,Vvsq]@Wa1+ba1)

__device__ __forceinline__ float silu_f(float x) {
    return x / (1.0f + __expf(-x));
}

__device__ __forceinline__ void red4(float* p, float a, float b, float c, float d) {
    asm volatile("red.global.add.v4.f32 [%0], {%1,%2,%3,%4};"
                 :: "l"(p), "f"(a), "f"(b), "f"(c), "f"(d) : "memory");
}

// ---------------- kernel 1: init output with residuals -----------------------
__global__ void k_init(const float* __restrict__ ns, const float* __restrict__ nv,
                       float* __restrict__ out) {
    const float4* a = (const float4*)ns;
    const float4* b = (const float4*)nv;
    float4* os = (float4*)out;
    float4* ov = os + (NN * D) / 4;
    const int ts = NN * D / 4;
    const int tv = NN * 3 * D / 4;
    for (int i = blockIdx.x * blockDim.x + threadIdx.x; i < ts; i += gridDim.x * blockDim.x)
        os[i] = a[i];
    for (int i = blockIdx.x * blockDim.x + threadIdx.x; i < tv; i += gridDim.x * blockDim.x)
        ov[i] = b[i];
}

// ---------------- kernel 2: h1 = silu(ns @ Wm1 + bm1) ------------------------
__global__ void k_mlp1(const float* __restrict__ x, const float* __restrict__ W,
                       const float* __restrict__ b) {
    extern __shared__ float sm[];
    float* Ws = sm;                 // 16384
    float* bs = sm + 16384;         // 128
    float* xs = sm + 16512;         // 512
    int tid = threadIdx.x, g = tid >> 7, c = tid & 127;
    for (int i = tid; i < D * D; i += 512) Ws[i] = W[i];
    if (tid < D) bs[tid] = b[tid];
    __syncthreads();
    int stride = gridDim.x * 4;
    int iters = (NN + stride - 1) / stride;
    for (int it = 0; it < iters; ++it) {
        int n = it * stride + blockIdx.x * 4 + g;
        bool act = n < NN;
        if (act) xs[g * D + c] = x[(long)n * D + c];
        __syncthreads();
        if (act) {
            float acc = bs[c];
#pragma unroll 8
            for (int k = 0; k < D; k++) acc += xs[g * D + k] * Ws[k * D + c];
            g_h1[(long)n * D + c] = silu_f(acc);
        }
        __syncthreads();
    }
}

// ---------------- kernel 3: scalar_output = h1 @ Wm2 + bm2 -------------------
// warp = 4 nodes, all 384 cols; lane owns 4 consecutive cols in each 128-block.
__global__ void __launch_bounds__(512, 1)
k_mlp2(const float* __restrict__ W, const float* __restrict__ b) {
    extern __shared__ float sm[];
    float* Ws = sm;                 // 49152
    float* bs = sm + 49152;         // 384
    int tid = threadIdx.x;
    {
        const float4* Wv = (const float4*)W;
        float4* Wsv = (float4*)Ws;
        for (int i = tid; i < 12288; i += 512) Wsv[i] = Wv[i];
        if (tid < 384) bs[tid] = b[tid];
    }
    __syncthreads();
    int warp = tid >> 5, lane = tid & 31;
    int n0 = blockIdx.x * 64 + warp * 4;

    float xr[4][4];
#pragma unroll
    for (int n = 0; n < 4; n++) {
        int node = n0 + n;
#pragma unroll
        for (int j = 0; j < 4; j++)
            xr[j][n] = (node < NN) ? g_h1[(size_t)node * D + j * 32 + lane] : 0.f;
    }
    float4 b0 = *(float4*)(bs + lane * 4);
    float4 b1 = *(float4*)(bs + 128 + lane * 4);
    float4 b2 = *(float4*)(bs + 256 + lane * 4);
    float4 a0[4], a1[4], a2[4];
#pragma unroll
    for (int n = 0; n < 4; n++) { a0[n] = b0; a1[n] = b1; a2[n] = b2; }

#pragma unroll
    for (int j = 0; j < 4; j++) {
#pragma unroll
        for (int kk = 0; kk < 32; kk++) {
            int k = j * 32 + kk;
            float4 w0 = *(float4*)(Ws + k * 384 + lane * 4);
            float4 w1 = *(float4*)(Ws + k * 384 + 128 + lane * 4);
            float4 w2 = *(float4*)(Ws + k * 384 + 256 + lane * 4);
#pragma unroll
            for (int n = 0; n < 4; n++) {
                float xv = __shfl_sync(0xffffffffu, xr[j][n], kk);
                a0[n].x += xv * w0.x; a0[n].y += xv * w0.y; a0[n].z += xv * w0.z; a0[n].w += xv * w0.w;
                a1[n].x += xv * w1.x; a1[n].y += xv * w1.y; a1[n].z += xv * w1.z; a1[n].w += xv * w1.w;
                a2[n].x += xv * w2.x; a2[n].y += xv * w2.y; a2[n].z += xv * w2.z; a2[n].w += xv * w2.w;
            }
        }
    }
#pragma unroll
    for (int n = 0; n < 4; n++) {
        int node = n0 + n;
        if (node < NN) {
            float* o = g_so + (size_t)node * 384 + lane * 4;
            *(float4*)o = a0[n];
            *(float4*)(o + 128) = a1[n];
            *(float4*)(o + 256) = a2[n];
        }
    }
}

// ---------------- kernel 4: fused edge filter + gather + scatter -------------
// Independent warps, 3 roles, NO barriers. role r owns Wf cols [r*128, r*128+128).
// role 0: gate_nodes * nv[src]  -> 3 red4 into out_v
// role 1: gate_edges * ev       -> 3 red4 into out_v
// role 2: messages_scalar       -> 1 red4 into out_s
__global__ void __launch_bounds__(480, 1)
k_edge(const float* __restrict__ es, const float* __restrict__ ev,
       const float* __restrict__ en, const int* __restrict__ ei,
       const float* __restrict__ Wf, const float* __restrict__ bf,
       const float* __restrict__ nv, float* __restrict__ out) {
    int gwarp = (blockIdx.x * blockDim.x + threadIdx.x) >> 5;
    int lane = threadIdx.x & 31;
    int trio = gwarp / 3, role = gwarp % 3;
    int ntrio = (gridDim.x * 480 / 32) / 3;      // 740

    float4 Wreg[ESZ];
    const float* wb = Wf + role * 128 + lane * 4;
#pragma unroll
    for (int k = 0; k < ESZ; k++) Wreg[k] = *(const float4*)(wb + k * 384);
    float4 bfr = *(const float4*)(bf + role * 128 + lane * 4);

    float* out_s = out;
    float* out_v = out + (size_t)NN * D;

    int e = trio;
    if (e >= NE) return;
    // prefetch first edge scalars
    float esv = (lane < ESZ) ? __ldg(es + (size_t)e * ESZ + lane) : 0.f;
    int src = __ldg(ei + 2 * (size_t)e);
    int dst = __ldg(ei + 2 * (size_t)e + 1);
    float r = __ldg(en + e);

    while (true) {
        int e2 = e + ntrio;
        float esv2 = 0.f; int src2 = 0, dst2 = 0; float r2 = 0.f;
        if (e2 < NE) {
            esv2 = (lane < ESZ) ? __ldg(es + (size_t)e2 * ESZ + lane) : 0.f;
            src2 = __ldg(ei + 2 * (size_t)e2);
            dst2 = __ldg(ei + 2 * (size_t)e2 + 1);
            r2 = __ldg(en + e2);
        }
        float fc = (r < 5.0f) ? 0.5f * (cospif(r * 0.2f) + 1.0f) : 0.0f;
        float4 f = bfr;
#pragma unroll
        for (int k = 0; k < ESZ; k++) {
            float ek = __shfl_sync(0xffffffffu, esv, k);
            f.x += ek * Wreg[k].x;
            f.y += ek * Wreg[k].y;
            f.z += ek * Wreg[k].z;
            f.w += ek * Wreg[k].w;
        }
        float4 so4 = __ldg((const float4*)(g_so + (size_t)src * 384 + role * 128) + lane);
        float4 m;
        m.x = f.x * fc * so4.x;
        m.y = f.y * fc * so4.y;
        m.z = f.z * fc * so4.z;
        m.w = f.w * fc * so4.w;

        if (role == 2) {
            red4(out_s + (size_t)dst * D + lane * 4, m.x, m.y, m.z, m.w);
        } else if (role == 1) {
            float ev0 = __ldg(ev + 3 * (size_t)e);
            float ev1 = __ldg(ev + 3 * (size_t)e + 1);
            float ev2 = __ldg(ev + 3 * (size_t)e + 2);
            float* ovb = out_v + (size_t)dst * 384 + lane * 4;
            red4(ovb,       m.x * ev0, m.y * ev0, m.z * ev0, m.w * ev0);
            red4(ovb + 128, m.x * ev1, m.y * ev1, m.z * ev1, m.w * ev1);
            red4(ovb + 256, m.x * ev2, m.y * ev2, m.z * ev2, m.w * ev2);
        } else {
            const float4* nvp = (const float4*)(nv + (size_t)src * 384) + lane;
            float4 n0 = __ldg(nvp);
            float4 n1 = __ldg(nvp + 32);
            float4 n2 = __ldg(nvp + 64);
            float* ovb = out_v + (size_t)dst * 384 + lane * 4;
            red4(ovb,       m.x * n0.x, m.y * n0.y, m.z * n0.z, m.w * n0.w);
            red4(ovb + 128, m.x * n1.x, m.y * n1.y, m.z * n1.z, m.w * n1.w);
            red4(ovb + 256, m.x * n2.x, m.y * n2.y, m.z * n2.z, m.w * n2.w);
        }
        if (e2 >= NE) break;
        e = e2; esv = esv2; src = src2; dst = dst2; r = r2;
    }
}

// ---------------- kernel 5: Uv, |Vv|^2, <Uv,Vv> ------------------------------
__global__ void k_uv(const float* __restrict__ WU, const float* __restrict__ WV,
                     const float* __restrict__ out) {
    extern __shared__ float sm[];
    float* WUs = sm;
    float* WVs = sm + 16384;
    float* vs = sm + 32768;
    const float* v_in = out + (long)NN * D;
    int tid = threadIdx.x, g = tid >> 7, c = tid & 127;
    for (int i = tid; i < 16384; i += 512) {
        WUs[i] = WU[i];
        WVs[i] = WV[i];
    }
    __syncthreads();
    int stride = gridDim.x * 4;
    int iters = (NN + stride - 1) / stride;
    for (int it = 0; it < iters; ++it) {
        int n = it * stride + blockIdx.x * 4 + g;
        bool act = n < NN;
        if (act) {
            long b = (long)n * 384;
            vs[g * 384 + c]       = v_in[b + c];
            vs[g * 384 + c + 128] = v_in[b + c + 128];
            vs[g * 384 + c + 256] = v_in[b + c + 256];
        }
        __syncthreads();
        if (act) {
            float u0 = 0, u1 = 0, u2 = 0, w0 = 0, w1 = 0, w2 = 0;
#pragma unroll 4
            for (int k = 0; k < D; k++) {
                float wu = WUs[k * D + c], wv = WVs[k * D + c];
                float v0 = vs[g * 384 + k];
                float v1 = vs[g * 384 + 128 + k];
                float v2 = vs[g * 384 + 256 + k];
                u0 += v0 * wu; u1 += v1 * wu; u2 += v2 * wu;
                w0 += v0 * wv; w1 += v1 * wv; w2 += v2 * wv;
            }
            long b = (long)n * 384;
            g_uv[b + c] = u0;
            g_uv[b + c + 128] = u1;
            g_uv[b + c + 256] = u2;
            g_vvsq[(long)n * D + c] = w0 * w0 + w1 * w1 + w2 * w2;
            g_ip[(long)n * D + c]   = u0 * w0 + u1 * w1 + u2 * w2;
        }
        __syncthreads();
    }
}

// ---------------- kernel 6: h2 = silu([s, Vvsq] @ Wa1 + ba1) -----------------
// warp = 4 nodes, 128 cols; lane owns 4 cols. K = 256.
__global__ void __launch_bounds__(512, 1)
k_a1(const float* __restrict__ W, const float* __restrict__ b,
     const float* __restrict__ out) {
    extern __shared__ float sm[];
    float* Ws = sm;                 // 32768
    float* bs = sm + 32768;         // 128
    int tid = threadIdx.x;
    {
        const float4* Wv = (const float4*)W;
        float4* Wsv = (float4*)Ws;
        for (int i = tid; i < 8192; i += 512) Wsv[i] = Wv[i];
        if (tid < 128) bs[tid] = b[tid];
    }
    __syncthreads();
    int warp = tid >> 5, lane = tid & 31;
    int n0 = blockIdx.x * 64 + warp * 4;

    float xr[8][4];
#pragma unroll
    for (int n = 0; n < 4; n++) {
        int node = n0 + n;
        if (node < NN) {
#pragma unroll
            for (int j = 0; j < 4; j++)
                xr[j][n] = out[(size_t)node * D + j * 32 + lane];
#pragma unroll
            for (int j = 0; j < 4; j++)
                xr[4 + j][n] = g_vvsq[(size_t)node * D + j * 32 + lane];
        } else {
#pragma unroll
            for (int j = 0; j < 8; j++) xr[j][n] = 0.f;
        }
    }
    float4 bv = *(float4*)(bs + lane * 4);
    float4 acc[4];
#pragma unroll
    for (int n = 0; n < 4; n++) acc[n] = bv;

#pragma unroll
    for (int j = 0; j < 8; j++) {
#pragma unroll
        for (int kk = 0; kk < 32; kk++) {
            int k = j * 32 + kk;
            float4 w = *(float4*)(Ws + k * D + lane * 4);
#pragma unroll
            for (int n = 0; n < 4; n++) {
                float xv = __shfl_sync(0xffffffffu, xr[j][n], kk);
                acc[n].x += xv * w.x; acc[n].y += xv * w.y;
                acc[n].z += xv * w.z; acc[n].w += xv * w.w;
            }
        }
    }
#pragma unroll
    for (int n = 0; n < 4; n++) {
        int node = n0 + n;
        if (node < NN) {
            float4 o;
            o.x = silu_f(acc[n].x); o.y = silu_f(acc[n].y);
            o.z = silu_f(acc[n].z); o.w = silu_f(acc[n].w);
            *(float4*)(g_h2 + (size_t)node * D + lane * 4) = o;
        }
    }
}

// ---------------- kernel 7: a = h2 @ Wa2 + ba2, final in-place update --------
__global__ void __launch_bounds__(512, 1)
k_a2(const float* __restrict__ W, const float* __restrict__ b,
     float* __restrict__ out) {
    extern __shared__ float sm[];
    float* Ws = sm;                 // 49152
    float* bs = sm + 49152;         // 384
    int tid = threadIdx.x;
    {
        const float4* Wv = (const float4*)W;
        float4* Wsv = (float4*)Ws;
        for (int i = tid; i < 12288; i += 512) Wsv[i] = Wv[i];
        if (tid < 384) bs[tid] = b[tid];
    }
    __syncthreads();
    int warp = tid >> 5, lane = tid & 31;
    int n0 = blockIdx.x * 64 + warp * 4;
    float* out_s = out;
    float* out_v = out + (size_t)NN * D;

    float xr[4][4];
#pragma unroll
    for (int n = 0; n < 4; n++) {
        int node = n0 + n;
#pragma unroll
        for (int j = 0; j < 4; j++)
            xr[j][n] = (node < NN) ? g_h2[(size_t)node * D + j * 32 + lane] : 0.f;
    }
    float4 b0 = *(float4*)(bs + lane * 4);
    float4 b1 = *(float4*)(bs + 128 + lane * 4);
    float4 b2 = *(float4*)(bs + 256 + lane * 4);
    float4 a0[4], a1[4], a2[4];
#pragma unroll
    for (int n = 0; n < 4; n++) { a0[n] = b0; a1[n] = b1; a2[n] = b2; }

#pragma unroll
    for (int j = 0; j < 4; j++) {
#pragma unroll
        for (int kk = 0; kk < 32; kk++) {
            int k = j * 32 + kk;
            float4 w0 = *(float4*)(Ws + k * 384 + lane * 4);
            float4 w1 = *(float4*)(Ws + k * 384 + 128 + lane * 4);
            float4 w2 = *(float4*)(Ws + k * 384 + 256 + lane * 4);
#pragma unroll
            for (int n = 0; n < 4; n++) {
                float xv = __shfl_sync(0xffffffffu, xr[j][n], kk);
                a0[n].x += xv * w0.x; a0[n].y += xv * w0.y; a0[n].z += xv * w0.z; a0[n].w += xv * w0.w;
                a1[n].x += xv * w1.x; a1[n].y += xv * w1.y; a1[n].z += xv * w1.z; a1[n].w += xv * w1.w;
                a2[n].x += xv * w2.x; a2[n].y += xv * w2.y; a2[n].z += xv * w2.z; a2[n].w += xv * w2.w;
            }
        }
    }
#pragma unroll
    for (int n = 0; n < 4; n++) {
        int node = n0 + n;
        if (node < NN) {
            float* sp = out_s + (size_t)node * D + lane * 4;
            float4 s = *(float4*)sp;
            float4 ip = *(float4*)(g_ip + (size_t)node * D + lane * 4);
            s.x += a0[n].x + a1[n].x * ip.x;
            s.y += a0[n].y + a1[n].y * ip.y;
            s.z += a0[n].z + a1[n].z * ip.z;
            s.w += a0[n].w + a1[n].w * ip.w;
            *(float4*)sp = s;
            const float* uvb = g_uv + (size_t)node * 384 + lane * 4;
            float* ovb = out_v + (size_t)node * 384 + lane * 4;
#pragma unroll
            for (int ax = 0; ax < 3; ax++) {
                float4 uv = *(const float4*)(uvb + ax * 128);
                float4 vv = *(float4*)(ovb + ax * 128);
                vv.x += a2[n].x * uv.x;
                vv.y += a2[n].y * uv.y;
                vv.z += a2[n].z * uv.z;
                vv.w += a2[n].w * uv.w;
                *(float4*)(ovb + ax * 128) = vv;
            }
        }
    }
}

// ---------------- launch ------------------------------------------------------
extern "C" void kernel_launch(void* const* d_in, const int* in_sizes, int n_in,
                              void* d_out, int out_size) {
    const float* ns  = (const float*)d_in[0];
    const float* nv  = (const float*)d_in[1];
    const float* es  = (const float*)d_in[2];
    const float* ev  = (const float*)d_in[3];
    const float* en  = (const float*)d_in[4];
    const int*   ei  = (const int*)d_in[5];
    const float* Wf  = (const float*)d_in[6];
    const float* bf  = (const float*)d_in[7];
    const float* Wm1 = (const float*)d_in[8];
    const float* bm1 = (const float*)d_in[9];
    const float* Wm2 = (const float*)d_in[10];
    const float* bm2 = (const float*)d_in[11];
    const float* WU  = (const float*)d_in[12];
    const float* WV  = (const float*)d_in[13];
    const float* Wa1 = (const float*)d_in[14];
    const float* ba1 = (const float*)d_in[15];
    const float* Wa2 = (const float*)d_in[16];
    const float* ba2 = (const float*)d_in[17];
    float* out = (float*)d_out;

    const int SM_MLP1 = (16384 + 128 + 512) * 4;
    const int SM_GEMM = (49152 + 384) * 4;        // mlp2 / a2
    const int SM_UV   = (32768 + 4 * 384) * 4;
    const int SM_A1   = (32768 + 128) * 4;

    cudaFuncSetAttribute(k_mlp1, cudaFuncAttributeMaxDynamicSharedMemorySize, SM_MLP1);
    cudaFuncSetAttribute(k_mlp2, cudaFuncAttributeMaxDynamicSharedMemorySize, SM_GEMM);
    cudaFuncSetAttribute(k_uv,   cudaFuncAttributeMaxDynamicSharedMemorySize, SM_UV);
    cudaFuncSetAttribute(k_a1,   cudaFuncAttributeMaxDynamicSharedMemorySize, SM_A1);
    cudaFuncSetAttribute(k_a2,   cudaFuncAttributeMaxDynamicSharedMemorySize, SM_GEMM);

    int gnode = (NN + 63) / 64;   // 313

    k_init<<<2048, 256>>>(ns, nv, out);
    k_mlp1<<<148, 512, SM_MLP1>>>(ns, Wm1, bm1);
    k_mlp2<<<gnode, 512, SM_GEMM>>>(Wm2, bm2);
    k_edge<<<148, 480>>>(es, ev, en, ei, Wf, bf, nv, out);
    k_uv<<<148, 512, SM_UV>>>(WU, WV, out);
    k_a1<<<gnode, 512, SM_A1>>>(Wa1, ba1, out);
    k_a2<<<gnode, 512, SM_GEMM>>>(Wa2, ba2, out);
}